// round 15
// baseline (speedup 1.0000x reference)
#include <cuda_runtime.h>
#include <stdint.h>

#define ND    10000
#define DIM   64
#define SS    16
#define EMAX  1000000
#define NBLK  592
#define NTHR  256
#define NWPB  8
#define NWARP (NBLK*NWPB)
#define CAP   192                // per-drug bucket capacity (deg ~ Poisson(100))
#define REGCAP 160               // fast-path selection capacity (5 keys/lane)
#define OVFCAP 8192
#define ABLK  1184               // scatter kernel blocks
#define ATHR  256
#define NTILE 625                // 625*16 == ND

typedef unsigned int u32;
typedef unsigned long long u64;

// ---------------------------------------------------------------- threefry2x32
__host__ __device__ __forceinline__ void threefry(u32 k0, u32 k1, u32 x0, u32 x1,
                                                  u32& o0, u32& o1) {
#ifdef __CUDA_ARCH__
#define TFR(a,b,r) { a += b; b = __funnelshift_l(b, b, r); b ^= a; }
#else
#define TFR(a,b,r) { a += b; b = (b<<r)|(b>>(32-r)); b ^= a; }
#endif
    u32 ks2 = k0 ^ k1 ^ 0x1BD11BDAu;
    x0 += k0; x1 += k1;
    TFR(x0,x1,13); TFR(x0,x1,15); TFR(x0,x1,26); TFR(x0,x1,6);
    x0 += k1; x1 += ks2 + 1u;
    TFR(x0,x1,17); TFR(x0,x1,29); TFR(x0,x1,16); TFR(x0,x1,24);
    x0 += ks2; x1 += k0 + 2u;
    TFR(x0,x1,13); TFR(x0,x1,15); TFR(x0,x1,26); TFR(x0,x1,6);
    x0 += k0; x1 += k1 + 3u;
    TFR(x0,x1,17); TFR(x0,x1,29); TFR(x0,x1,16); TFR(x0,x1,24);
    x0 += k1; x1 += ks2 + 4u;
    TFR(x0,x1,13); TFR(x0,x1,15); TFR(x0,x1,26); TFR(x0,x1,6);
    x0 += ks2; x1 += k0 + 5u;
    o0 = x0; o1 = x1;
#undef TFR
}
__device__ __forceinline__ u32 rbits_stream(u32 kx, u32 ky, int i) {
    u32 a, b; threefry(kx, ky, 0u, (u32)i, a, b);
    return a ^ b;
}

// ---------------------------------------------------------------- scratch
__device__ int   g_cursor[ND];               // zero at launch; re-zeroed at end
__device__ u64   g_bucket[(size_t)ND*CAP];   // rank(23)|edge(20)
__device__ int   g_ovfCnt;
__device__ u64   g_ovf[OVFCAP];
__device__ float g_neigh[ND*DIM];
__device__ float g_psum[NBLK*DIM];
__device__ float g_psq[NBLK*DIM];
__device__ float g_A[DIM];
__device__ float g_B[DIM];
__device__ float g_w2s[DIM];
__device__ float g_b2s;
__device__ u32   g_bar_count;
__device__ u32   g_bar_gen;                  // monotonic across replays
__device__ u32   g_work;

// ---------------------------------------------------------------- f32x2 helpers
__device__ __forceinline__ u64 pack2(float lo, float hi) {
    u64 r;
    asm("mov.b64 %0, {%1, %2};" : "=l"(r) : "f"(lo), "f"(hi));
    return r;
}
__device__ __forceinline__ void unpack2(u64 v, float& lo, float& hi) {
    asm("mov.b64 {%0, %1}, %2;" : "=f"(lo), "=f"(hi) : "l"(v));
}
__device__ __forceinline__ void fma2(u64& acc, u64 a, u64 b) {
    asm("fma.rn.f32x2 %0, %1, %2, %0;" : "+l"(acc) : "l"(a), "l"(b));
}
__device__ __forceinline__ u64 umin64(u64 a, u64 b) { return a < b ? a : b; }

// ================================================================ scatter kernel
// 4-edge batching: 3x LDG.128 per thread for DKG, 4 independent atomics,
// 4 independent threefry chains, 4 stores -> MLP=4 on the atomic chain.
__global__ void scatter_kernel(const int* __restrict__ DKG,
                               const float* __restrict__ HF,
                               const float* __restrict__ X,
                               const float* __restrict__ W2,
                               const float* __restrict__ b2,
                               float* __restrict__ outBase,
                               int E, int hf_n, int x_n,
                               u32 k1x, u32 k1y) {
    const int gtid = blockIdx.x * ATHR + threadIdx.x;
    const int nth  = ABLK * ATHR;

    {
        const float4* hf4 = (const float4*)HF;
        float4* o4 = (float4*)outBase;
        for (int t = gtid; t < hf_n/4; t += nth) o4[t] = hf4[t];
        const float4* x4 = (const float4*)X;
        float4* ox4 = (float4*)(outBase + hf_n + ND*DIM);
        for (int t = gtid; t < x_n/4; t += nth) ox4[t] = x4[t];
    }
    if (blockIdx.x == ABLK - 1) {
        int t = threadIdx.x;
        if (t < DIM) {
            float s = 0.f;
            for (int j = 0; j < DIM; j++) s += W2[t*DIM + j];
            g_w2s[t] = s;
        }
        if (t == DIM) {
            float s = 0.f;
            for (int j = 0; j < DIM; j++) s += b2[j];
            g_b2s = s;
        }
    }

    const int E4 = E & ~3;
    for (int e = gtid*4; e < E4; e += nth*4) {
        // 12 ints = 3 aligned int4 (byte offset 12e, e%4==0 => 16B aligned)
        const int4* p = (const int4*)(DKG + 3*e);
        int4 v0 = p[0];
        int4 v1 = p[1];
        int4 v2 = p[2];
        int h0 = v0.x, h1 = v0.w, h2 = v1.z, h3 = v2.y;
        // 4 independent atomics in flight
        int s0 = atomicAdd(&g_cursor[h0], 1);
        int s1 = atomicAdd(&g_cursor[h1], 1);
        int s2 = atomicAdd(&g_cursor[h2], 1);
        int s3 = atomicAdd(&g_cursor[h3], 1);
        // 4 independent threefry chains (overlap the atomic returns)
        u32 a0, b0, a1, b1, a2, b2v, a3, b3;
        threefry(k1x, k1y, 0u, (u32)(e + 0), a0, b0);
        threefry(k1x, k1y, 0u, (u32)(e + 1), a1, b1);
        threefry(k1x, k1y, 0u, (u32)(e + 2), a2, b2v);
        threefry(k1x, k1y, 0u, (u32)(e + 3), a3, b3);
        u64 key0 = (((u64)((a0 ^ b0)  >> 9)) << 20) | (u32)(e + 0);
        u64 key1 = (((u64)((a1 ^ b1)  >> 9)) << 20) | (u32)(e + 1);
        u64 key2 = (((u64)((a2 ^ b2v) >> 9)) << 20) | (u32)(e + 2);
        u64 key3 = (((u64)((a3 ^ b3)  >> 9)) << 20) | (u32)(e + 3);
        if (s0 < CAP) g_bucket[(size_t)h0*CAP + s0] = key0;
        else { int o = atomicAdd(&g_ovfCnt, 1); if (o < OVFCAP) g_ovf[o] = ((u64)h0 << 43) | key0; }
        if (s1 < CAP) g_bucket[(size_t)h1*CAP + s1] = key1;
        else { int o = atomicAdd(&g_ovfCnt, 1); if (o < OVFCAP) g_ovf[o] = ((u64)h1 << 43) | key1; }
        if (s2 < CAP) g_bucket[(size_t)h2*CAP + s2] = key2;
        else { int o = atomicAdd(&g_ovfCnt, 1); if (o < OVFCAP) g_ovf[o] = ((u64)h2 << 43) | key2; }
        if (s3 < CAP) g_bucket[(size_t)h3*CAP + s3] = key3;
        else { int o = atomicAdd(&g_ovfCnt, 1); if (o < OVFCAP) g_ovf[o] = ((u64)h3 << 43) | key3; }
    }
    // remainder (E not multiple of 4)
    for (int e = E4 + gtid; e < E; e += nth) {
        int h = DKG[3*e];
        int slot = atomicAdd(&g_cursor[h], 1);
        u32 bits = rbits_stream(k1x, k1y, e);
        u64 key = (((u64)(bits >> 9)) << 20) | (u32)e;
        if (slot < CAP) g_bucket[(size_t)h*CAP + slot] = key;
        else { int o = atomicAdd(&g_ovfCnt, 1); if (o < OVFCAP) g_ovf[o] = ((u64)h << 43) | key; }
    }
}

// ---------------------------------------------------------------- shared layout
// phase B: [0,16384) w1pk2 | [16384) b1s | [16640) w2ss | [16896,33280) hb2 8w*2KB (ssel aliases)
// phase C: [0,32768) wcp2 | [32768,33792) red | [33792,41984) xbuf 8w*1KB
#define SH_BYTES (42*1024)

__global__ void __launch_bounds__(NTHR, 4)
mega_kernel(const int* __restrict__ DKG,
            const float* __restrict__ drug_emb,
            const float* __restrict__ rel_emb,
            const float* __restrict__ tail_emb,
            const float* __restrict__ W1,
            const float* __restrict__ b1,
            const float* __restrict__ Wc,
            const float* __restrict__ bc,
            const float* __restrict__ gamma,
            const float* __restrict__ beta,
            float* __restrict__ out,
            u32 kLx, u32 kLy) {
    __shared__ __align__(16) char sh_raw[SH_BYTES];
    __shared__ u32 s_gen;

    const int tid  = threadIdx.x;
    const int bid  = blockIdx.x;
    const int gtid = bid * NTHR + tid;
    const int nth  = NBLK * NTHR;
    const int lane = tid & 31;
    const int wid  = tid >> 5;

    if (tid == 0) s_gen = *((volatile u32*)&g_bar_gen);

    auto gsync = [&]() {
        __syncthreads();
        if (tid == 0) {
            u32 target = s_gen + 1;
            __threadfence();
            u32 t = atomicAdd(&g_bar_count, 1u);
            if (t == (u32)NBLK - 1) {
                atomicExch(&g_bar_count, 0u);
                __threadfence();
                atomicExch(&g_bar_gen, target);
            } else {
                volatile u32* vg = &g_bar_gen;
                while (*vg < target) { }
            }
            __threadfence();
            s_gen = target;
        }
        __syncthreads();
    };

    // ============ phase B fused: select top16 + score + aggregate ============
    {
        ulonglong2* w1pk2 = (ulonglong2*)sh_raw;      // [ip*32+lane]
        float* b1s   = (float*)(sh_raw + 16384);
        float* w2ss  = (float*)(sh_raw + 16640);
        ulonglong2* hb2 = (ulonglong2*)(sh_raw + 16896) + wid * 128;  // 2KB/warp
        int*   ssel  = (int*)(sh_raw + 16896 + wid * 2048);  // aliases hb2 (disjoint use)

        for (int i = tid; i < 32*32; i += NTHR) {
            int ip = i >> 5, ln = i & 31;
            ulonglong2 v;
            v.x = pack2(W1[(2*ip)*DIM + ln],      W1[(2*ip + 1)*DIM + ln]);
            v.y = pack2(W1[(2*ip)*DIM + 32 + ln], W1[(2*ip + 1)*DIM + 32 + ln]);
            w1pk2[i] = v;
        }
        if (tid < DIM)        b1s[tid] = b1[tid];
        else if (tid < 2*DIM) w2ss[tid - DIM] = g_w2s[tid - DIM];
        __syncthreads();
        const float b2s = g_b2s;
        const u64 FULLK = ~0ULL;

        for (;;) {
            int d;
            if (lane == 0) d = (int)atomicAdd(&g_work, 1u);
            d = __shfl_sync(0xffffffffu, d, 0);
            if (d >= ND) break;

            const int degd = g_cursor[d];
            const int cnt  = (degd < SS) ? degd : SS;
            const u64* bkt = g_bucket + (size_t)d*CAP;

            if (degd >= SS && degd <= REGCAP) {
                // ================= FAST PATH (cnt == 16) =================
                u64 c0 = (lane       < degd) ? bkt[lane]       : FULLK;
                u64 c1 = (lane + 32  < degd) ? bkt[lane + 32]  : FULLK;
                u64 c2 = (lane + 64  < degd) ? bkt[lane + 64]  : FULLK;
                u64 c3 = (lane + 96  < degd) ? bkt[lane + 96]  : FULLK;
                u64 c4 = (lane + 128 < degd) ? bkt[lane + 128] : FULLK;
                u64 lmin = umin64(umin64(umin64(c0, c1), umin64(c2, c3)), c4);
                int tail = 0, rel = 0;
                #pragma unroll
                for (int r = 0; r < SS; r++) {
                    u32 hi = (u32)(lmin >> 11);
                    u32 mhi = __reduce_min_sync(0xffffffffu, hi);
                    u32 bal = __ballot_sync(0xffffffffu, hi == mhi);
                    u64 m;
                    if (__popc(bal) == 1) {
                        m = __shfl_sync(0xffffffffu, lmin, __ffs(bal) - 1);
                    } else {
                        m = lmin;
                        #pragma unroll
                        for (int o = 16; o; o >>= 1)
                            m = umin64(m, __shfl_xor_sync(0xffffffffu, m, o));
                    }
                    int er = (int)(m & 0xFFFFFu);
                    if (lane == r) {
                        tail = DKG[3*er + 1];
                        rel  = DKG[3*er + 2];
                    }
                    if (lmin == m) {
                        if      (c0 == m) c0 = FULLK;
                        else if (c1 == m) c1 = FULLK;
                        else if (c2 == m) c2 = FULLK;
                        else if (c3 == m) c3 = FULLK;
                        else              c4 = FULLK;
                        lmin = umin64(umin64(umin64(c0, c1), umin64(c2, c3)), c4);
                    }
                }

                const float2 de2 = ((const float2*)(drug_emb + d*DIM))[lane];
                const u64 bin0 = pack2(b1s[lane], 0.f);
                const u64 bin1 = pack2(b1s[lane + 32], 0.f);
                const float w20 = w2ss[lane], w21 = w2ss[lane + 32];

                float myscore = 0.f;
                #pragma unroll
                for (int kb = 0; kb < 2; kb++) {
                    const int kbase = kb * 8;
                    {
                        u64 h[8];
                        #pragma unroll
                        for (int u = 0; u < 8; u++) {
                            int rr = __shfl_sync(0xffffffffu, rel, kbase + u);
                            float2 re = ((const float2*)(rel_emb + rr*DIM))[lane];
                            h[u] = pack2(de2.x*re.x, de2.y*re.y);
                        }
                        #pragma unroll
                        for (int p = 0; p < 4; p++) {
                            ulonglong2 hp; hp.x = h[2*p]; hp.y = h[2*p + 1];
                            hb2[p*32 + lane] = hp;          // STS.128
                        }
                    }
                    __syncwarp();
                    u64 a0[8], a1[8];
                    #pragma unroll
                    for (int u = 0; u < 8; u++) { a0[u] = bin0; a1[u] = bin1; }
                    #pragma unroll
                    for (int ip = 0; ip < 32; ip++) {
                        ulonglong2 wv = w1pk2[ip*32 + lane];   // LDS.128
                        #pragma unroll
                        for (int p = 0; p < 4; p++) {
                            ulonglong2 hp = hb2[p*32 + ip];    // LDS.128 broadcast
                            fma2(a0[2*p],     hp.x, wv.x);
                            fma2(a1[2*p],     hp.x, wv.y);
                            fma2(a0[2*p + 1], hp.y, wv.x);
                            fma2(a1[2*p + 1], hp.y, wv.y);
                        }
                    }
                    __syncwarp();
                    #pragma unroll
                    for (int u = 0; u < 8; u++) {
                        float e0, o0, e1, o1;
                        unpack2(a0[u], e0, o0);
                        unpack2(a1[u], e1, o1);
                        float p = (1.f/(1.f+__expf(-(e0+o0))))*w20
                                + (1.f/(1.f+__expf(-(e1+o1))))*w21;
                        #pragma unroll
                        for (int o = 16; o; o >>= 1)
                            p += __shfl_xor_sync(0xffffffffu, p, o);
                        if (lane == kbase + u) myscore = p + b2s;
                    }
                }

                // ---- packed aggregation: lanes own columns (2lane, 2lane+1) ----
                u64 accP = pack2(0.f, 0.f);
                #pragma unroll
                for (int k = 0; k < SS; k++) {
                    float sc = __shfl_sync(0xffffffffu, myscore, k);
                    int   t  = __shfl_sync(0xffffffffu, tail, k);
                    u64 te = ((const u64*)(tail_emb + t*DIM))[lane];
                    fma2(accP, pack2(sc, sc), te);
                }
                ((u64*)(g_neigh + d*DIM))[lane] = accP;

            } else if (cnt > 0) {
                // ================= SLOW PATH =================
                int myedge = 0;
                if (degd <= REGCAP) {
                    u64 c0 = (lane       < degd) ? bkt[lane]       : FULLK;
                    u64 c1 = (lane + 32  < degd) ? bkt[lane + 32]  : FULLK;
                    u64 c2 = (lane + 64  < degd) ? bkt[lane + 64]  : FULLK;
                    u64 c3 = (lane + 96  < degd) ? bkt[lane + 96]  : FULLK;
                    u64 c4 = (lane + 128 < degd) ? bkt[lane + 128] : FULLK;
                    u64 lmin = umin64(umin64(umin64(c0, c1), umin64(c2, c3)), c4);
                    for (int r = 0; r < cnt; r++) {
                        u64 m = lmin;
                        #pragma unroll
                        for (int o = 16; o; o >>= 1) {
                            u64 t = __shfl_xor_sync(0xffffffffu, m, o);
                            m = umin64(m, t);
                        }
                        if (lane == r) myedge = (int)(m & 0xFFFFFu);
                        if (lmin == m) {
                            if      (c0 == m) c0 = FULLK;
                            else if (c1 == m) c1 = FULLK;
                            else if (c2 == m) c2 = FULLK;
                            else if (c3 == m) c3 = FULLK;
                            else              c4 = FULLK;
                            lmin = umin64(umin64(umin64(c0, c1), umin64(c2, c3)), c4);
                        }
                    }
                } else {
                    int nb = (degd < CAP) ? degd : CAP;
                    int novf = g_ovfCnt; if (novf > OVFCAP) novf = OVFCAP;
                    for (int t = lane; t < nb; t += 32) {
                        u64 k = bkt[t];
                        int rank = 0;
                        for (int j = 0; j < nb; j++) rank += (bkt[j] < k);
                        for (int o = 0; o < novf; o++) {
                            u64 v = g_ovf[o];
                            if ((int)(v >> 43) == d) rank += ((v & 0x7FFFFFFFFFFULL) < k);
                        }
                        if (rank < SS) ssel[rank] = (int)(k & 0xFFFFFu);
                    }
                    for (int t = lane; t < novf; t += 32) {
                        u64 v = g_ovf[t];
                        if ((int)(v >> 43) == d) {
                            u64 k = v & 0x7FFFFFFFFFFULL;
                            int rank = 0;
                            for (int j = 0; j < nb; j++) rank += (bkt[j] < k);
                            for (int o = 0; o < novf; o++) {
                                u64 w = g_ovf[o];
                                if ((int)(w >> 43) == d) rank += ((w & 0x7FFFFFFFFFFULL) < k);
                            }
                            if (rank < SS) ssel[rank] = (int)(k & 0xFFFFFu);
                        }
                    }
                    __syncwarp();
                    if (lane < cnt) myedge = ssel[lane];
                }

                int tail = 0, rel = 0;
                if (lane < cnt) {
                    tail = DKG[3*myedge + 1];
                    rel  = DKG[3*myedge + 2];
                }
                __syncwarp();

                const float2 de2 = ((const float2*)(drug_emb + d*DIM))[lane];
                const u64 bin0 = pack2(b1s[lane], 0.f);
                const u64 bin1 = pack2(b1s[lane + 32], 0.f);
                const float w20 = w2ss[lane], w21 = w2ss[lane + 32];

                float myscore = 0.f;
                for (int k = 0; k < cnt; k++) {
                    int rA = __shfl_sync(0xffffffffu, rel, k);
                    float2 reA = ((const float2*)(rel_emb + rA*DIM))[lane];
                    u64 hA = pack2(de2.x*reA.x, de2.y*reA.y);
                    u64 aA0 = bin0, aA1 = bin1;
                    #pragma unroll
                    for (int ip = 0; ip < 32; ip++) {
                        ulonglong2 wv = w1pk2[ip*32 + lane];
                        u64 hb = __shfl_sync(0xffffffffu, hA, ip);
                        fma2(aA0, hb, wv.x); fma2(aA1, hb, wv.y);
                    }
                    float e0, o0, e1, o1;
                    unpack2(aA0, e0, o0); unpack2(aA1, e1, o1);
                    float pA = (1.f/(1.f+__expf(-(e0+o0))))*w20
                             + (1.f/(1.f+__expf(-(e1+o1))))*w21;
                    #pragma unroll
                    for (int o = 16; o; o >>= 1) pA += __shfl_xor_sync(0xffffffffu, pA, o);
                    if (lane == k) myscore = pA + b2s;
                }

                u64 accP = pack2(0.f, 0.f);
                for (int k = 0; k < cnt; k++) {
                    float sc = __shfl_sync(0xffffffffu, myscore, k);
                    int   t  = __shfl_sync(0xffffffffu, tail, k);
                    u64 te = ((const u64*)(tail_emb + t*DIM))[lane];
                    fma2(accP, pack2(sc, sc), te);
                }
                if (degd < SS) {
                    for (int s = 0; s < SS - degd; s++) {
                        u32 bits = rbits_stream(kLx, kLy, d*SS + s);
                        int idx = (int)((bits % 2147483647u) % (u32)degd);
                        float sc = __shfl_sync(0xffffffffu, myscore, idx);
                        int   t  = __shfl_sync(0xffffffffu, tail, idx);
                        u64 te = ((const u64*)(tail_emb + t*DIM))[lane];
                        fma2(accP, pack2(sc, sc), te);
                    }
                }
                ((u64*)(g_neigh + d*DIM))[lane] = accP;
            } else {
                ((u64*)(g_neigh + d*DIM))[lane] = 0ULL;
            }
        }
    }
    gsync();

    // ============ phase C: y = [drug_emb, neigh] @ Wc + bc (y stays in registers) ============
    float yv[2][4];                       // up to 2 tiles per block, 4 y values each
    int   yrow[2] = { -1, -1 };
    {
        if (gtid == 0) { g_work = 0; g_ovfCnt = 0; }   // replay-state reset
        ulonglong2* wcp2 = (ulonglong2*)sh_raw;        // 32KB
        float* red = (float*)(sh_raw + 32768);         // 1KB
        u64*   xb  = (u64*)(sh_raw + 33792) + wid * 128;  // 1KB/warp
        for (int i = tid; i < 64*32; i += NTHR) {
            int i2 = i >> 5, o = i & 31;
            ulonglong2 v;
            v.x = pack2(Wc[(2*i2)*DIM + o],     Wc[(2*i2)*DIM + o + 32]);
            v.y = pack2(Wc[(2*i2 + 1)*DIM + o], Wc[(2*i2 + 1)*DIM + o + 32]);
            wcp2[i] = v;
        }
        __syncthreads();
        const int o = lane;
        const u64 bcv = pack2(bc[o], bc[o + 32]);
        float S0 = 0.f, S1 = 0.f, Q0 = 0.f, Q1 = 0.f;
        #pragma unroll
        for (int it = 0; it < 2; it++) {
            int r16 = bid + it * NBLK;
            if (r16 >= NTILE) break;
            int row0 = r16*16 + wid;
            int row1 = row0 + 8;
            yrow[it] = row0;
            xb[lane]      = ((const u64*)(drug_emb + row0*DIM))[lane];
            xb[32 + lane] = ((const u64*)(g_neigh  + row0*DIM))[lane];
            xb[64 + lane] = ((const u64*)(drug_emb + row1*DIM))[lane];
            xb[96 + lane] = ((const u64*)(g_neigh  + row1*DIM))[lane];
            __syncwarp();
            u64 accR0 = bcv, accR1 = bcv;
            #pragma unroll
            for (int i2 = 0; i2 < 32; i2++) {
                ulonglong2 wv = wcp2[i2*32 + o];
                u64 dA = xb[i2];
                u64 dB = xb[64 + i2];
                float vA0, vA1, vB0, vB1;
                unpack2(dA, vA0, vA1);
                unpack2(dB, vB0, vB1);
                fma2(accR0, pack2(vA0, vA0), wv.x);
                fma2(accR0, pack2(vA1, vA1), wv.y);
                fma2(accR1, pack2(vB0, vB0), wv.x);
                fma2(accR1, pack2(vB1, vB1), wv.y);
            }
            #pragma unroll
            for (int i2 = 0; i2 < 32; i2++) {
                ulonglong2 wv = wcp2[(32 + i2)*32 + o];
                u64 dA = xb[32 + i2];
                u64 dB = xb[96 + i2];
                float vA0, vA1, vB0, vB1;
                unpack2(dA, vA0, vA1);
                unpack2(dB, vB0, vB1);
                fma2(accR0, pack2(vA0, vA0), wv.x);
                fma2(accR0, pack2(vA1, vA1), wv.y);
                fma2(accR1, pack2(vB0, vB0), wv.x);
                fma2(accR1, pack2(vB1, vB1), wv.y);
            }
            __syncwarp();
            float y00, y01, y10, y11;
            unpack2(accR0, y00, y01);
            unpack2(accR1, y10, y11);
            yv[it][0] = y00; yv[it][1] = y01; yv[it][2] = y10; yv[it][3] = y11;
            S0 += y00 + y10;
            S1 += y01 + y11;
            Q0 += y00*y00 + y10*y10;
            Q1 += y01*y01 + y11*y11;
        }
        red[tid] = S0;
        __syncthreads();
        if (tid < 32) { float s = 0.f;
            #pragma unroll
            for (int p = 0; p < 8; p++) s += red[p*32 + lane];
            g_psum[bid*DIM + lane] = s; }
        __syncthreads();
        red[tid] = S1;
        __syncthreads();
        if (tid < 32) { float s = 0.f;
            #pragma unroll
            for (int p = 0; p < 8; p++) s += red[p*32 + lane];
            g_psum[bid*DIM + 32 + lane] = s; }
        __syncthreads();
        red[tid] = Q0;
        __syncthreads();
        if (tid < 32) { float s = 0.f;
            #pragma unroll
            for (int p = 0; p < 8; p++) s += red[p*32 + lane];
            g_psq[bid*DIM + lane] = s; }
        __syncthreads();
        red[tid] = Q1;
        __syncthreads();
        if (tid < 32) { float s = 0.f;
            #pragma unroll
            for (int p = 0; p < 8; p++) s += red[p*32 + lane];
            g_psq[bid*DIM + 32 + lane] = s; }
    }
    gsync();

    // ============ phase D1: per-column BN stats (64 blocks) ============
    if (bid < DIM) {
        float* rs = (float*)sh_raw;
        float* rq = (float*)(sh_raw + 1024);
        const int col = bid;
        float s = 0.f, q = 0.f;
        for (int b = tid; b < NBLK; b += NTHR) {
            s += g_psum[b*DIM + col];
            q += g_psq[b*DIM + col];
        }
        rs[tid] = s; rq[tid] = q;
        __syncthreads();
        for (int ofs = NTHR/2; ofs > 0; ofs >>= 1) {
            if (tid < ofs) { rs[tid] += rs[tid + ofs]; rq[tid] += rq[tid + ofs]; }
            __syncthreads();
        }
        if (tid == 0) {
            float mean = rs[0] / (float)ND;
            float var  = rq[0] / (float)ND - mean * mean;
            float rstd = rsqrtf(var + 1e-5f);
            float gm = gamma[col];
            g_A[col] = gm * rstd;
            g_B[col] = beta[col] - gm * mean * rstd;
        }
    }
    gsync();

    // ============ phase D2: normalize registers + write + state reset ============
    {
        float* A = (float*)sh_raw;
        float* B = (float*)(sh_raw + 256);
        if (tid < DIM)        A[tid] = g_A[tid];
        else if (tid < 2*DIM) B[tid - DIM] = g_B[tid - DIM];
        __syncthreads();

        const float A0 = A[lane],      B0 = B[lane];
        const float A1 = A[lane + 32], B1 = B[lane + 32];
        #pragma unroll
        for (int it = 0; it < 2; it++) {
            int row0 = yrow[it];
            if (row0 < 0) break;
            int row1 = row0 + 8;
            out[row0*DIM + lane]      = fmaf(yv[it][0], A0, B0);
            out[row0*DIM + 32 + lane] = fmaf(yv[it][1], A1, B1);
            out[row1*DIM + lane]      = fmaf(yv[it][2], A0, B0);
            out[row1*DIM + 32 + lane] = fmaf(yv[it][3], A1, B1);
        }

        // replay-state reset: g_cursor must be zero for next replay's scatter
        for (int i = gtid; i < ND; i += nth) g_cursor[i] = 0;
    }
}

// ---------------------------------------------------------------- host
static void compute_keys(u32& k1x, u32& k1y, u32& kLx, u32& kLy) {
    u32 a, b, c, d, e, f;
    threefry(0u, 42u, 0u, 0u, a, b);   // k1 = split(key(42))[0]
    k1x = a; k1y = b;
    threefry(0u, 42u, 0u, 1u, c, d);   // k2 = split(key(42))[1]
    threefry(c, d, 0u, 1u, e, f);      // split(k2)[1]
    kLx = e; kLy = f;
}

extern "C" void kernel_launch(void* const* d_in, const int* in_sizes, int n_in,
                              void* d_out, int out_size) {
    const float* HF       = (const float*)d_in[0];
    const float* X        = (const float*)d_in[1];
    const float* drug_emb = (const float*)d_in[2];
    const float* rel_emb  = (const float*)d_in[3];
    const float* tail_emb = (const float*)d_in[4];
    const float* W1       = (const float*)d_in[5];
    const float* b1       = (const float*)d_in[6];
    const float* W2       = (const float*)d_in[7];
    const float* b2       = (const float*)d_in[8];
    const float* Wc       = (const float*)d_in[9];
    const float* bc       = (const float*)d_in[10];
    const float* gamma    = (const float*)d_in[11];
    const float* beta     = (const float*)d_in[12];
    const int*   DKG      = (const int*)d_in[13];
    int E    = in_sizes[13] / 3;
    int hf_n = in_sizes[0];
    int x_n  = in_sizes[1];
    float* out = (float*)d_out;

    u32 k1x, k1y, kLx, kLy;
    compute_keys(k1x, k1y, kLx, kLy);

    scatter_kernel<<<ABLK, ATHR>>>(DKG, HF, X, W2, b2, out, E, hf_n, x_n, k1x, k1y);
    mega_kernel<<<NBLK, NTHR>>>(DKG, drug_emb, rel_emb, tail_emb, W1, b1,
                                Wc, bc, gamma, beta, out + hf_n, kLx, kLy);
}

// round 16
// speedup vs baseline: 1.0601x; 1.0601x over previous
#include <cuda_runtime.h>
#include <stdint.h>

#define ND    10000
#define DIM   64
#define SS    16
#define EMAX  1000000
#define NBLK  592
#define NTHR  256
#define NWPB  8
#define NWARP (NBLK*NWPB)
#define CAP   192                // per-drug bucket capacity (deg ~ Poisson(100))
#define REGCAP 160               // fast-path selection capacity (5 keys/lane)
#define OVFCAP 8192
#define ABLK  1184               // scatter kernel blocks
#define ATHR  256
#define NTILE 625                // 625*16 == ND

typedef unsigned int u32;
typedef unsigned long long u64;

// ---------------------------------------------------------------- threefry2x32
__host__ __device__ __forceinline__ void threefry(u32 k0, u32 k1, u32 x0, u32 x1,
                                                  u32& o0, u32& o1) {
#ifdef __CUDA_ARCH__
#define TFR(a,b,r) { a += b; b = __funnelshift_l(b, b, r); b ^= a; }
#else
#define TFR(a,b,r) { a += b; b = (b<<r)|(b>>(32-r)); b ^= a; }
#endif
    u32 ks2 = k0 ^ k1 ^ 0x1BD11BDAu;
    x0 += k0; x1 += k1;
    TFR(x0,x1,13); TFR(x0,x1,15); TFR(x0,x1,26); TFR(x0,x1,6);
    x0 += k1; x1 += ks2 + 1u;
    TFR(x0,x1,17); TFR(x0,x1,29); TFR(x0,x1,16); TFR(x0,x1,24);
    x0 += ks2; x1 += k0 + 2u;
    TFR(x0,x1,13); TFR(x0,x1,15); TFR(x0,x1,26); TFR(x0,x1,6);
    x0 += k0; x1 += k1 + 3u;
    TFR(x0,x1,17); TFR(x0,x1,29); TFR(x0,x1,16); TFR(x0,x1,24);
    x0 += k1; x1 += ks2 + 4u;
    TFR(x0,x1,13); TFR(x0,x1,15); TFR(x0,x1,26); TFR(x0,x1,6);
    x0 += ks2; x1 += k0 + 5u;
    o0 = x0; o1 = x1;
#undef TFR
}
__device__ __forceinline__ u32 rbits_stream(u32 kx, u32 ky, int i) {
    u32 a, b; threefry(kx, ky, 0u, (u32)i, a, b);
    return a ^ b;
}

// ---------------------------------------------------------------- scratch
__device__ int   g_cursor[ND];               // zero at launch; re-zeroed at end
__device__ u64   g_bucket[(size_t)ND*CAP];   // rank(23)|edge(20)
__device__ int   g_ovfCnt;
__device__ u64   g_ovf[OVFCAP];
__device__ float g_neigh[ND*DIM];
__device__ float g_psum[NBLK*DIM];
__device__ float g_psq[NBLK*DIM];
__device__ float g_A[DIM];
__device__ float g_B[DIM];
__device__ float g_w2s[DIM];
__device__ float g_b2s;
__device__ u32   g_bar_count;
__device__ u32   g_bar_gen;                  // monotonic across replays
__device__ u32   g_work;

// ---------------------------------------------------------------- f32x2 helpers
__device__ __forceinline__ u64 pack2(float lo, float hi) {
    u64 r;
    asm("mov.b64 %0, {%1, %2};" : "=l"(r) : "f"(lo), "f"(hi));
    return r;
}
__device__ __forceinline__ void unpack2(u64 v, float& lo, float& hi) {
    asm("mov.b64 {%0, %1}, %2;" : "=f"(lo), "=f"(hi) : "l"(v));
}
__device__ __forceinline__ void fma2(u64& acc, u64 a, u64 b) {
    asm("fma.rn.f32x2 %0, %1, %2, %0;" : "+l"(acc) : "l"(a), "l"(b));
}
__device__ __forceinline__ u64 umin64(u64 a, u64 b) { return a < b ? a : b; }

// ================================================================ scatter kernel
// Grid-stride with 4-way unroll: coalesced-pattern loads (same sectors as the
// 2-edge version) but 4 independent LDG->ATOMG->STG chains per thread.
__global__ void scatter_kernel(const int* __restrict__ DKG,
                               const float* __restrict__ HF,
                               const float* __restrict__ X,
                               const float* __restrict__ W2,
                               const float* __restrict__ b2,
                               float* __restrict__ outBase,
                               int E, int hf_n, int x_n,
                               u32 k1x, u32 k1y) {
    const int gtid = blockIdx.x * ATHR + threadIdx.x;
    const int nth  = ABLK * ATHR;

    {
        const float4* hf4 = (const float4*)HF;
        float4* o4 = (float4*)outBase;
        for (int t = gtid; t < hf_n/4; t += nth) o4[t] = hf4[t];
        const float4* x4 = (const float4*)X;
        float4* ox4 = (float4*)(outBase + hf_n + ND*DIM);
        for (int t = gtid; t < x_n/4; t += nth) ox4[t] = x4[t];
    }
    if (blockIdx.x == ABLK - 1) {
        int t = threadIdx.x;
        if (t < DIM) {
            float s = 0.f;
            for (int j = 0; j < DIM; j++) s += W2[t*DIM + j];
            g_w2s[t] = s;
        }
        if (t == DIM) {
            float s = 0.f;
            for (int j = 0; j < DIM; j++) s += b2[j];
            g_b2s = s;
        }
    }

    #pragma unroll 4
    for (int e = gtid; e < E; e += nth) {
        int h = DKG[3*e];
        int slot = atomicAdd(&g_cursor[h], 1);
        u32 a, b;
        threefry(k1x, k1y, 0u, (u32)e, a, b);
        u64 key = (((u64)((a ^ b) >> 9)) << 20) | (u32)e;
        if (slot < CAP) g_bucket[(size_t)h*CAP + slot] = key;
        else {
            int o = atomicAdd(&g_ovfCnt, 1);
            if (o < OVFCAP) g_ovf[o] = ((u64)h << 43) | key;
        }
    }
}

// ---------------------------------------------------------------- shared layout
// phase B: [0,16384) w1pk2 | [16384) b1s | [16640) w2ss | [16896,33280) hb2 8w*2KB (ssel aliases)
// phase C: [0,32768) wcp2 | [32768,33792) red | [33792,41984) xbuf 8w*1KB
#define SH_BYTES (42*1024)

__global__ void __launch_bounds__(NTHR, 4)
mega_kernel(const int* __restrict__ DKG,
            const float* __restrict__ drug_emb,
            const float* __restrict__ rel_emb,
            const float* __restrict__ tail_emb,
            const float* __restrict__ W1,
            const float* __restrict__ b1,
            const float* __restrict__ Wc,
            const float* __restrict__ bc,
            const float* __restrict__ gamma,
            const float* __restrict__ beta,
            float* __restrict__ out,
            u32 kLx, u32 kLy) {
    __shared__ __align__(16) char sh_raw[SH_BYTES];
    __shared__ u32 s_gen;

    const int tid  = threadIdx.x;
    const int bid  = blockIdx.x;
    const int gtid = bid * NTHR + tid;
    const int nth  = NBLK * NTHR;
    const int lane = tid & 31;
    const int wid  = tid >> 5;

    if (tid == 0) s_gen = *((volatile u32*)&g_bar_gen);

    auto gsync = [&]() {
        __syncthreads();
        if (tid == 0) {
            u32 target = s_gen + 1;
            __threadfence();
            u32 t = atomicAdd(&g_bar_count, 1u);
            if (t == (u32)NBLK - 1) {
                atomicExch(&g_bar_count, 0u);
                __threadfence();
                atomicExch(&g_bar_gen, target);
            } else {
                volatile u32* vg = &g_bar_gen;
                while (*vg < target) { }
            }
            __threadfence();
            s_gen = target;
        }
        __syncthreads();
    };

    // ============ phase B fused: select top16 + score + aggregate ============
    {
        ulonglong2* w1pk2 = (ulonglong2*)sh_raw;      // [ip*32+lane]
        float* b1s   = (float*)(sh_raw + 16384);
        float* w2ss  = (float*)(sh_raw + 16640);
        ulonglong2* hb2 = (ulonglong2*)(sh_raw + 16896) + wid * 128;  // 2KB/warp
        int*   ssel  = (int*)(sh_raw + 16896 + wid * 2048);  // aliases hb2 (disjoint use)

        for (int i = tid; i < 32*32; i += NTHR) {
            int ip = i >> 5, ln = i & 31;
            ulonglong2 v;
            v.x = pack2(W1[(2*ip)*DIM + ln],      W1[(2*ip + 1)*DIM + ln]);
            v.y = pack2(W1[(2*ip)*DIM + 32 + ln], W1[(2*ip + 1)*DIM + 32 + ln]);
            w1pk2[i] = v;
        }
        if (tid < DIM)        b1s[tid] = b1[tid];
        else if (tid < 2*DIM) w2ss[tid - DIM] = g_w2s[tid - DIM];
        __syncthreads();
        const float b2s = g_b2s;
        const u64 FULLK = ~0ULL;

        for (;;) {
            int d;
            if (lane == 0) d = (int)atomicAdd(&g_work, 1u);
            d = __shfl_sync(0xffffffffu, d, 0);
            if (d >= ND) break;

            const int degd = g_cursor[d];
            const int cnt  = (degd < SS) ? degd : SS;
            const u64* bkt = g_bucket + (size_t)d*CAP;

            if (degd >= SS && degd <= REGCAP) {
                // ================= FAST PATH (cnt == 16) =================
                u64 c0 = (lane       < degd) ? bkt[lane]       : FULLK;
                u64 c1 = (lane + 32  < degd) ? bkt[lane + 32]  : FULLK;
                u64 c2 = (lane + 64  < degd) ? bkt[lane + 64]  : FULLK;
                u64 c3 = (lane + 96  < degd) ? bkt[lane + 96]  : FULLK;
                u64 c4 = (lane + 128 < degd) ? bkt[lane + 128] : FULLK;
                u64 lmin = umin64(umin64(umin64(c0, c1), umin64(c2, c3)), c4);
                int tail = 0, rel = 0;
                #pragma unroll
                for (int r = 0; r < SS; r++) {
                    u32 hi = (u32)(lmin >> 11);
                    u32 mhi = __reduce_min_sync(0xffffffffu, hi);
                    u32 bal = __ballot_sync(0xffffffffu, hi == mhi);
                    u64 m;
                    if (__popc(bal) == 1) {
                        m = __shfl_sync(0xffffffffu, lmin, __ffs(bal) - 1);
                    } else {
                        m = lmin;
                        #pragma unroll
                        for (int o = 16; o; o >>= 1)
                            m = umin64(m, __shfl_xor_sync(0xffffffffu, m, o));
                    }
                    int er = (int)(m & 0xFFFFFu);
                    if (lane == r) {
                        tail = DKG[3*er + 1];
                        rel  = DKG[3*er + 2];
                    }
                    if (lmin == m) {
                        if      (c0 == m) c0 = FULLK;
                        else if (c1 == m) c1 = FULLK;
                        else if (c2 == m) c2 = FULLK;
                        else if (c3 == m) c3 = FULLK;
                        else              c4 = FULLK;
                        lmin = umin64(umin64(umin64(c0, c1), umin64(c2, c3)), c4);
                    }
                }

                const float2 de2 = ((const float2*)(drug_emb + d*DIM))[lane];
                const u64 bin0 = pack2(b1s[lane], 0.f);
                const u64 bin1 = pack2(b1s[lane + 32], 0.f);
                const float w20 = w2ss[lane], w21 = w2ss[lane + 32];

                float myscore = 0.f;
                #pragma unroll
                for (int kb = 0; kb < 2; kb++) {
                    const int kbase = kb * 8;
                    {
                        u64 h[8];
                        #pragma unroll
                        for (int u = 0; u < 8; u++) {
                            int rr = __shfl_sync(0xffffffffu, rel, kbase + u);
                            float2 re = ((const float2*)(rel_emb + rr*DIM))[lane];
                            h[u] = pack2(de2.x*re.x, de2.y*re.y);
                        }
                        #pragma unroll
                        for (int p = 0; p < 4; p++) {
                            ulonglong2 hp; hp.x = h[2*p]; hp.y = h[2*p + 1];
                            hb2[p*32 + lane] = hp;          // STS.128
                        }
                    }
                    __syncwarp();
                    u64 a0[8], a1[8];
                    #pragma unroll
                    for (int u = 0; u < 8; u++) { a0[u] = bin0; a1[u] = bin1; }
                    #pragma unroll
                    for (int ip = 0; ip < 32; ip++) {
                        ulonglong2 wv = w1pk2[ip*32 + lane];   // LDS.128
                        #pragma unroll
                        for (int p = 0; p < 4; p++) {
                            ulonglong2 hp = hb2[p*32 + ip];    // LDS.128 broadcast
                            fma2(a0[2*p],     hp.x, wv.x);
                            fma2(a1[2*p],     hp.x, wv.y);
                            fma2(a0[2*p + 1], hp.y, wv.x);
                            fma2(a1[2*p + 1], hp.y, wv.y);
                        }
                    }
                    __syncwarp();
                    #pragma unroll
                    for (int u = 0; u < 8; u++) {
                        float e0, o0, e1, o1;
                        unpack2(a0[u], e0, o0);
                        unpack2(a1[u], e1, o1);
                        float p = (1.f/(1.f+__expf(-(e0+o0))))*w20
                                + (1.f/(1.f+__expf(-(e1+o1))))*w21;
                        #pragma unroll
                        for (int o = 16; o; o >>= 1)
                            p += __shfl_xor_sync(0xffffffffu, p, o);
                        if (lane == kbase + u) myscore = p + b2s;
                    }
                }

                // ---- packed aggregation: lanes own columns (2lane, 2lane+1) ----
                u64 accP = pack2(0.f, 0.f);
                #pragma unroll
                for (int k = 0; k < SS; k++) {
                    float sc = __shfl_sync(0xffffffffu, myscore, k);
                    int   t  = __shfl_sync(0xffffffffu, tail, k);
                    u64 te = ((const u64*)(tail_emb + t*DIM))[lane];
                    fma2(accP, pack2(sc, sc), te);
                }
                ((u64*)(g_neigh + d*DIM))[lane] = accP;

            } else if (cnt > 0) {
                // ================= SLOW PATH =================
                int myedge = 0;
                if (degd <= REGCAP) {
                    u64 c0 = (lane       < degd) ? bkt[lane]       : FULLK;
                    u64 c1 = (lane + 32  < degd) ? bkt[lane + 32]  : FULLK;
                    u64 c2 = (lane + 64  < degd) ? bkt[lane + 64]  : FULLK;
                    u64 c3 = (lane + 96  < degd) ? bkt[lane + 96]  : FULLK;
                    u64 c4 = (lane + 128 < degd) ? bkt[lane + 128] : FULLK;
                    u64 lmin = umin64(umin64(umin64(c0, c1), umin64(c2, c3)), c4);
                    for (int r = 0; r < cnt; r++) {
                        u64 m = lmin;
                        #pragma unroll
                        for (int o = 16; o; o >>= 1) {
                            u64 t = __shfl_xor_sync(0xffffffffu, m, o);
                            m = umin64(m, t);
                        }
                        if (lane == r) myedge = (int)(m & 0xFFFFFu);
                        if (lmin == m) {
                            if      (c0 == m) c0 = FULLK;
                            else if (c1 == m) c1 = FULLK;
                            else if (c2 == m) c2 = FULLK;
                            else if (c3 == m) c3 = FULLK;
                            else              c4 = FULLK;
                            lmin = umin64(umin64(umin64(c0, c1), umin64(c2, c3)), c4);
                        }
                    }
                } else {
                    int nb = (degd < CAP) ? degd : CAP;
                    int novf = g_ovfCnt; if (novf > OVFCAP) novf = OVFCAP;
                    for (int t = lane; t < nb; t += 32) {
                        u64 k = bkt[t];
                        int rank = 0;
                        for (int j = 0; j < nb; j++) rank += (bkt[j] < k);
                        for (int o = 0; o < novf; o++) {
                            u64 v = g_ovf[o];
                            if ((int)(v >> 43) == d) rank += ((v & 0x7FFFFFFFFFFULL) < k);
                        }
                        if (rank < SS) ssel[rank] = (int)(k & 0xFFFFFu);
                    }
                    for (int t = lane; t < novf; t += 32) {
                        u64 v = g_ovf[t];
                        if ((int)(v >> 43) == d) {
                            u64 k = v & 0x7FFFFFFFFFFULL;
                            int rank = 0;
                            for (int j = 0; j < nb; j++) rank += (bkt[j] < k);
                            for (int o = 0; o < novf; o++) {
                                u64 w = g_ovf[o];
                                if ((int)(w >> 43) == d) rank += ((w & 0x7FFFFFFFFFFULL) < k);
                            }
                            if (rank < SS) ssel[rank] = (int)(k & 0xFFFFFu);
                        }
                    }
                    __syncwarp();
                    if (lane < cnt) myedge = ssel[lane];
                }

                int tail = 0, rel = 0;
                if (lane < cnt) {
                    tail = DKG[3*myedge + 1];
                    rel  = DKG[3*myedge + 2];
                }
                __syncwarp();

                const float2 de2 = ((const float2*)(drug_emb + d*DIM))[lane];
                const u64 bin0 = pack2(b1s[lane], 0.f);
                const u64 bin1 = pack2(b1s[lane + 32], 0.f);
                const float w20 = w2ss[lane], w21 = w2ss[lane + 32];

                float myscore = 0.f;
                for (int k = 0; k < cnt; k++) {
                    int rA = __shfl_sync(0xffffffffu, rel, k);
                    float2 reA = ((const float2*)(rel_emb + rA*DIM))[lane];
                    u64 hA = pack2(de2.x*reA.x, de2.y*reA.y);
                    u64 aA0 = bin0, aA1 = bin1;
                    #pragma unroll
                    for (int ip = 0; ip < 32; ip++) {
                        ulonglong2 wv = w1pk2[ip*32 + lane];
                        u64 hb = __shfl_sync(0xffffffffu, hA, ip);
                        fma2(aA0, hb, wv.x); fma2(aA1, hb, wv.y);
                    }
                    float e0, o0, e1, o1;
                    unpack2(aA0, e0, o0); unpack2(aA1, e1, o1);
                    float pA = (1.f/(1.f+__expf(-(e0+o0))))*w20
                             + (1.f/(1.f+__expf(-(e1+o1))))*w21;
                    #pragma unroll
                    for (int o = 16; o; o >>= 1) pA += __shfl_xor_sync(0xffffffffu, pA, o);
                    if (lane == k) myscore = pA + b2s;
                }

                u64 accP = pack2(0.f, 0.f);
                for (int k = 0; k < cnt; k++) {
                    float sc = __shfl_sync(0xffffffffu, myscore, k);
                    int   t  = __shfl_sync(0xffffffffu, tail, k);
                    u64 te = ((const u64*)(tail_emb + t*DIM))[lane];
                    fma2(accP, pack2(sc, sc), te);
                }
                if (degd < SS) {
                    for (int s = 0; s < SS - degd; s++) {
                        u32 bits = rbits_stream(kLx, kLy, d*SS + s);
                        int idx = (int)((bits % 2147483647u) % (u32)degd);
                        float sc = __shfl_sync(0xffffffffu, myscore, idx);
                        int   t  = __shfl_sync(0xffffffffu, tail, idx);
                        u64 te = ((const u64*)(tail_emb + t*DIM))[lane];
                        fma2(accP, pack2(sc, sc), te);
                    }
                }
                ((u64*)(g_neigh + d*DIM))[lane] = accP;
            } else {
                ((u64*)(g_neigh + d*DIM))[lane] = 0ULL;
            }
        }
    }
    gsync();

    // ============ phase C: y = [drug_emb, neigh] @ Wc + bc (y stays in registers) ============
    float yv[2][4];                       // up to 2 tiles per block, 4 y values each
    int   yrow[2] = { -1, -1 };
    {
        if (gtid == 0) { g_work = 0; g_ovfCnt = 0; }   // replay-state reset
        ulonglong2* wcp2 = (ulonglong2*)sh_raw;        // 32KB
        float* red = (float*)(sh_raw + 32768);         // 1KB
        u64*   xb  = (u64*)(sh_raw + 33792) + wid * 128;  // 1KB/warp
        for (int i = tid; i < 64*32; i += NTHR) {
            int i2 = i >> 5, o = i & 31;
            ulonglong2 v;
            v.x = pack2(Wc[(2*i2)*DIM + o],     Wc[(2*i2)*DIM + o + 32]);
            v.y = pack2(Wc[(2*i2 + 1)*DIM + o], Wc[(2*i2 + 1)*DIM + o + 32]);
            wcp2[i] = v;
        }
        __syncthreads();
        const int o = lane;
        const u64 bcv = pack2(bc[o], bc[o + 32]);
        float S0 = 0.f, S1 = 0.f, Q0 = 0.f, Q1 = 0.f;
        #pragma unroll
        for (int it = 0; it < 2; it++) {
            int r16 = bid + it * NBLK;
            if (r16 >= NTILE) break;
            int row0 = r16*16 + wid;
            int row1 = row0 + 8;
            yrow[it] = row0;
            xb[lane]      = ((const u64*)(drug_emb + row0*DIM))[lane];
            xb[32 + lane] = ((const u64*)(g_neigh  + row0*DIM))[lane];
            xb[64 + lane] = ((const u64*)(drug_emb + row1*DIM))[lane];
            xb[96 + lane] = ((const u64*)(g_neigh  + row1*DIM))[lane];
            __syncwarp();
            u64 accR0 = bcv, accR1 = bcv;
            #pragma unroll
            for (int i2 = 0; i2 < 32; i2++) {
                ulonglong2 wv = wcp2[i2*32 + o];
                u64 dA = xb[i2];
                u64 dB = xb[64 + i2];
                float vA0, vA1, vB0, vB1;
                unpack2(dA, vA0, vA1);
                unpack2(dB, vB0, vB1);
                fma2(accR0, pack2(vA0, vA0), wv.x);
                fma2(accR0, pack2(vA1, vA1), wv.y);
                fma2(accR1, pack2(vB0, vB0), wv.x);
                fma2(accR1, pack2(vB1, vB1), wv.y);
            }
            #pragma unroll
            for (int i2 = 0; i2 < 32; i2++) {
                ulonglong2 wv = wcp2[(32 + i2)*32 + o];
                u64 dA = xb[32 + i2];
                u64 dB = xb[96 + i2];
                float vA0, vA1, vB0, vB1;
                unpack2(dA, vA0, vA1);
                unpack2(dB, vB0, vB1);
                fma2(accR0, pack2(vA0, vA0), wv.x);
                fma2(accR0, pack2(vA1, vA1), wv.y);
                fma2(accR1, pack2(vB0, vB0), wv.x);
                fma2(accR1, pack2(vB1, vB1), wv.y);
            }
            __syncwarp();
            float y00, y01, y10, y11;
            unpack2(accR0, y00, y01);
            unpack2(accR1, y10, y11);
            yv[it][0] = y00; yv[it][1] = y01; yv[it][2] = y10; yv[it][3] = y11;
            S0 += y00 + y10;
            S1 += y01 + y11;
            Q0 += y00*y00 + y10*y10;
            Q1 += y01*y01 + y11*y11;
        }
        red[tid] = S0;
        __syncthreads();
        if (tid < 32) { float s = 0.f;
            #pragma unroll
            for (int p = 0; p < 8; p++) s += red[p*32 + lane];
            g_psum[bid*DIM + lane] = s; }
        __syncthreads();
        red[tid] = S1;
        __syncthreads();
        if (tid < 32) { float s = 0.f;
            #pragma unroll
            for (int p = 0; p < 8; p++) s += red[p*32 + lane];
            g_psum[bid*DIM + 32 + lane] = s; }
        __syncthreads();
        red[tid] = Q0;
        __syncthreads();
        if (tid < 32) { float s = 0.f;
            #pragma unroll
            for (int p = 0; p < 8; p++) s += red[p*32 + lane];
            g_psq[bid*DIM + lane] = s; }
        __syncthreads();
        red[tid] = Q1;
        __syncthreads();
        if (tid < 32) { float s = 0.f;
            #pragma unroll
            for (int p = 0; p < 8; p++) s += red[p*32 + lane];
            g_psq[bid*DIM + 32 + lane] = s; }
    }
    gsync();

    // ============ phase D1: per-column BN stats (64 blocks) ============
    if (bid < DIM) {
        float* rs = (float*)sh_raw;
        float* rq = (float*)(sh_raw + 1024);
        const int col = bid;
        float s = 0.f, q = 0.f;
        for (int b = tid; b < NBLK; b += NTHR) {
            s += g_psum[b*DIM + col];
            q += g_psq[b*DIM + col];
        }
        rs[tid] = s; rq[tid] = q;
        __syncthreads();
        for (int ofs = NTHR/2; ofs > 0; ofs >>= 1) {
            if (tid < ofs) { rs[tid] += rs[tid + ofs]; rq[tid] += rq[tid + ofs]; }
            __syncthreads();
        }
        if (tid == 0) {
            float mean = rs[0] / (float)ND;
            float var  = rq[0] / (float)ND - mean * mean;
            float rstd = rsqrtf(var + 1e-5f);
            float gm = gamma[col];
            g_A[col] = gm * rstd;
            g_B[col] = beta[col] - gm * mean * rstd;
        }
    }
    gsync();

    // ============ phase D2: normalize registers + write + state reset ============
    {
        float* A = (float*)sh_raw;
        float* B = (float*)(sh_raw + 256);
        if (tid < DIM)        A[tid] = g_A[tid];
        else if (tid < 2*DIM) B[tid - DIM] = g_B[tid - DIM];
        __syncthreads();

        const float A0 = A[lane],      B0 = B[lane];
        const float A1 = A[lane + 32], B1 = B[lane + 32];
        #pragma unroll
        for (int it = 0; it < 2; it++) {
            int row0 = yrow[it];
            if (row0 < 0) break;
            int row1 = row0 + 8;
            out[row0*DIM + lane]      = fmaf(yv[it][0], A0, B0);
            out[row0*DIM + 32 + lane] = fmaf(yv[it][1], A1, B1);
            out[row1*DIM + lane]      = fmaf(yv[it][2], A0, B0);
            out[row1*DIM + 32 + lane] = fmaf(yv[it][3], A1, B1);
        }

        // replay-state reset: g_cursor must be zero for next replay's scatter
        for (int i = gtid; i < ND; i += nth) g_cursor[i] = 0;
    }
}

// ---------------------------------------------------------------- host
static void compute_keys(u32& k1x, u32& k1y, u32& kLx, u32& kLy) {
    u32 a, b, c, d, e, f;
    threefry(0u, 42u, 0u, 0u, a, b);   // k1 = split(key(42))[0]
    k1x = a; k1y = b;
    threefry(0u, 42u, 0u, 1u, c, d);   // k2 = split(key(42))[1]
    threefry(c, d, 0u, 1u, e, f);      // split(k2)[1]
    kLx = e; kLy = f;
}

extern "C" void kernel_launch(void* const* d_in, const int* in_sizes, int n_in,
                              void* d_out, int out_size) {
    const float* HF       = (const float*)d_in[0];
    const float* X        = (const float*)d_in[1];
    const float* drug_emb = (const float*)d_in[2];
    const float* rel_emb  = (const float*)d_in[3];
    const float* tail_emb = (const float*)d_in[4];
    const float* W1       = (const float*)d_in[5];
    const float* b1       = (const float*)d_in[6];
    const float* W2       = (const float*)d_in[7];
    const float* b2       = (const float*)d_in[8];
    const float* Wc       = (const float*)d_in[9];
    const float* bc       = (const float*)d_in[10];
    const float* gamma    = (const float*)d_in[11];
    const float* beta     = (const float*)d_in[12];
    const int*   DKG      = (const int*)d_in[13];
    int E    = in_sizes[13] / 3;
    int hf_n = in_sizes[0];
    int x_n  = in_sizes[1];
    float* out = (float*)d_out;

    u32 k1x, k1y, kLx, kLy;
    compute_keys(k1x, k1y, kLx, kLy);

    scatter_kernel<<<ABLK, ATHR>>>(DKG, HF, X, W2, b2, out, E, hf_n, x_n, k1x, k1y);
    mega_kernel<<<NBLK, NTHR>>>(DKG, drug_emb, rel_emb, tail_emb, W1, b1,
                                Wc, bc, gamma, beta, out + hf_n, kLx, kLy);
}